// round 4
// baseline (speedup 1.0000x reference)
#include <cuda_runtime.h>
#include <cuda_bf16.h>
#include <cstdint>
#include <cstddef>

// ----------------------------------------------------------------------------
// Problem:
//   x[T,D] -> enc = x @ enc_w^T + enc_b            (T=4096, D=1024, P=512)
//   enc_n = enc / max(||enc||, 1e-8)
//   pat_n = patterns / max(||patterns||, 1e-8)     (N=65536)
//   sim = enc_n @ pat_n^T                          [T, N]
//   idx = top-128(sim)  (ties -> smallest index)
//   mean_pat = mean(patterns[idx], axis=1)         [T, P]
//   out = x + alpha * (mean_pat @ dec_w^T + dec_b) [T, D]
// ----------------------------------------------------------------------------

#define T_TOK 4096
#define D_DIM 1024
#define P_DIM 512
#define N_PAT 65536
#define K_TOP 128

// Static scratch (no runtime allocation).
__device__ float g_enc  [(size_t)T_TOK * P_DIM];
__device__ float g_encn [(size_t)T_TOK * P_DIM];
__device__ float g_patn [(size_t)N_PAT * P_DIM];
__device__ float g_sim  [(size_t)T_TOK * N_PAT];     // 1 GiB
__device__ int   g_topk [(size_t)T_TOK * K_TOP];
__device__ float g_mean [(size_t)T_TOK * P_DIM];

// ============================================================================
// Generic tiled SGEMM: C[M,N] = A[M,K] @ B[N,K]^T  (both K-major / row-major)
// BM=BN=128, BK=16, 256 threads, 8x8 per thread.
// MODE 0: C = acc                      (sim)
// MODE 1: C = acc + bias[n]           (encoder)
// MODE 2: C = resid + alpha*(acc+bias[n])  (decoder + residual)
// All dims must be multiples of 128 (M,N) and 16 (K) — true for all 3 calls.
// ============================================================================
template <int MODE>
__global__ __launch_bounds__(256, 2)
void gemm128_kernel(const float* __restrict__ A, const float* __restrict__ B,
                    const float* __restrict__ bias, float* __restrict__ C,
                    const float* __restrict__ resid, const float* __restrict__ alpha,
                    int M, int N, int K)
{
    __shared__ float As[16][128];
    __shared__ float Bs[16][128];

    const int tid = threadIdx.x;
    const int m0 = blockIdx.y * 128;
    const int n0 = blockIdx.x * 128;

    const int tr = tid >> 4;   // 0..15
    const int tc = tid & 15;   // 0..15

    float acc[8][8];
#pragma unroll
    for (int i = 0; i < 8; i++)
#pragma unroll
        for (int j = 0; j < 8; j++) acc[i][j] = 0.0f;

    // float4 load mapping: 512 float4s per tile, 2 per thread.
    const int f0_row = tid >> 2;          // 0..63   (first float4)
    const int f0_c4  = tid & 3;           // 0..3
    const int f1_row = (tid + 256) >> 2;  // 64..127
    const int f1_c4  = f0_c4;

    for (int k0 = 0; k0 < K; k0 += 16) {
        // load A tile (rows m0.., cols k0..k0+15), store k-major transposed
        {
            float4 v0 = *reinterpret_cast<const float4*>(&A[(size_t)(m0 + f0_row) * K + k0 + 4 * f0_c4]);
            float4 v1 = *reinterpret_cast<const float4*>(&A[(size_t)(m0 + f1_row) * K + k0 + 4 * f1_c4]);
            As[4 * f0_c4 + 0][f0_row] = v0.x;
            As[4 * f0_c4 + 1][f0_row] = v0.y;
            As[4 * f0_c4 + 2][f0_row] = v0.z;
            As[4 * f0_c4 + 3][f0_row] = v0.w;
            As[4 * f1_c4 + 0][f1_row] = v1.x;
            As[4 * f1_c4 + 1][f1_row] = v1.y;
            As[4 * f1_c4 + 2][f1_row] = v1.z;
            As[4 * f1_c4 + 3][f1_row] = v1.w;
        }
        // load B tile (rows n0.., cols k0..k0+15)
        {
            float4 v0 = *reinterpret_cast<const float4*>(&B[(size_t)(n0 + f0_row) * K + k0 + 4 * f0_c4]);
            float4 v1 = *reinterpret_cast<const float4*>(&B[(size_t)(n0 + f1_row) * K + k0 + 4 * f1_c4]);
            Bs[4 * f0_c4 + 0][f0_row] = v0.x;
            Bs[4 * f0_c4 + 1][f0_row] = v0.y;
            Bs[4 * f0_c4 + 2][f0_row] = v0.z;
            Bs[4 * f0_c4 + 3][f0_row] = v0.w;
            Bs[4 * f1_c4 + 0][f1_row] = v1.x;
            Bs[4 * f1_c4 + 1][f1_row] = v1.y;
            Bs[4 * f1_c4 + 2][f1_row] = v1.z;
            Bs[4 * f1_c4 + 3][f1_row] = v1.w;
        }
        __syncthreads();

#pragma unroll
        for (int k = 0; k < 16; k++) {
            float ra[8], rb[8];
            float4 a0 = *reinterpret_cast<const float4*>(&As[k][tr * 8 + 0]);
            float4 a1 = *reinterpret_cast<const float4*>(&As[k][tr * 8 + 4]);
            float4 b0 = *reinterpret_cast<const float4*>(&Bs[k][tc * 8 + 0]);
            float4 b1 = *reinterpret_cast<const float4*>(&Bs[k][tc * 8 + 4]);
            ra[0] = a0.x; ra[1] = a0.y; ra[2] = a0.z; ra[3] = a0.w;
            ra[4] = a1.x; ra[5] = a1.y; ra[6] = a1.z; ra[7] = a1.w;
            rb[0] = b0.x; rb[1] = b0.y; rb[2] = b0.z; rb[3] = b0.w;
            rb[4] = b1.x; rb[5] = b1.y; rb[6] = b1.z; rb[7] = b1.w;
#pragma unroll
            for (int i = 0; i < 8; i++)
#pragma unroll
                for (int j = 0; j < 8; j++)
                    acc[i][j] = fmaf(ra[i], rb[j], acc[i][j]);
        }
        __syncthreads();
    }

    const float a_val = (MODE == 2) ? alpha[0] : 0.0f;

#pragma unroll
    for (int i = 0; i < 8; i++) {
        const int m = m0 + tr * 8 + i;
#pragma unroll
        for (int j = 0; j < 8; j++) {
            const int n = n0 + tc * 8 + j;
            const size_t off = (size_t)m * N + n;
            float v = acc[i][j];
            if (MODE == 1) {
                v += bias[n];
            } else if (MODE == 2) {
                v = resid[off] + a_val * (v + bias[n]);
            }
            C[off] = v;
        }
    }
}

// ============================================================================
// Row L2-normalize: out[r][c] = in[r][c] / max(||in[r]||, 1e-8). cols = 512.
// One block (256 threads) per row.
// ============================================================================
__global__ void rownorm_kernel(const float* __restrict__ in, float* __restrict__ out,
                               int cols)
{
    const int r = blockIdx.x;
    const int tid = threadIdx.x;
    const float* row = in + (size_t)r * cols;

    float ss = 0.0f;
    for (int c = tid; c < cols; c += 256) {
        float v = row[c];
        ss = fmaf(v, v, ss);
    }
    // warp + block reduce
#pragma unroll
    for (int o = 16; o > 0; o >>= 1) ss += __shfl_xor_sync(0xFFFFFFFFu, ss, o);
    __shared__ float wsum[8];
    if ((tid & 31) == 0) wsum[tid >> 5] = ss;
    __syncthreads();
    if (tid < 32) {
        float v = (tid < 8) ? wsum[tid] : 0.0f;
#pragma unroll
        for (int o = 4; o > 0; o >>= 1) v += __shfl_xor_sync(0xFFFFFFFFu, v, o);
        if (tid == 0) wsum[0] = v;
    }
    __syncthreads();
    const float inv = 1.0f / fmaxf(sqrtf(wsum[0]), 1e-8f);

    float* orow = out + (size_t)r * cols;
    for (int c = tid; c < cols; c += 256) orow[c] = row[c] * inv;
}

// ============================================================================
// Exact top-128 per token via 4-pass radix select on order-preserving uint keys.
// Ties at the threshold value resolved by smallest index (jax top_k semantics;
// downstream only consumes the SET of indices, so order is irrelevant).
// One block (256 threads) per token.
// ============================================================================
__device__ __forceinline__ unsigned f2ord(float f) {
    unsigned x = __float_as_uint(f);
    return x ^ ((x & 0x80000000u) ? 0xFFFFFFFFu : 0x80000000u);
}

#define EQ_CAP 512

__global__ __launch_bounds__(256)
void topk_kernel(const float* __restrict__ sim, int* __restrict__ topk)
{
    const int t = blockIdx.x;
    const int tid = threadIdx.x;
    const float* row = sim + (size_t)t * N_PAT;

    __shared__ unsigned hist[256];
    __shared__ unsigned s_prefix;
    __shared__ int s_want;
    __shared__ int s_cg, s_ce;
    __shared__ int sel[K_TOP];
    __shared__ int eq[EQ_CAP];

    if (tid == 0) { s_prefix = 0u; s_want = K_TOP; }
    __syncthreads();

    // 4 radix passes, MSB first
    for (int shift = 24; shift >= 0; shift -= 8) {
        hist[tid] = 0u;
        __syncthreads();
        const unsigned mask_hi = (shift == 24) ? 0u : ~((1u << (shift + 8)) - 1u);
        const unsigned pfx = s_prefix;
#pragma unroll 4
        for (int i = 0; i < N_PAT / 256; i++) {
            unsigned u = f2ord(row[i * 256 + tid]);
            if ((u & mask_hi) == pfx)
                atomicAdd(&hist[(u >> shift) & 255u], 1u);
        }
        __syncthreads();
        if (tid == 0) {
            unsigned cum = 0;
            int want = s_want;
            for (int b = 255; b >= 0; b--) {
                unsigned c = hist[b];
                if (cum + c >= (unsigned)want) {
                    s_prefix = pfx | ((unsigned)b << shift);
                    s_want = want - (int)cum;
                    break;
                }
                cum += c;
            }
        }
        __syncthreads();
    }

    const unsigned tau = s_prefix;      // exact key of the boundary value
    const int want_eq = s_want;         // how many ties (== tau) to include

    if (tid == 0) { s_cg = 0; s_ce = 0; }
    __syncthreads();

    for (int i = 0; i < N_PAT / 256; i++) {
        const int idx = i * 256 + tid;
        unsigned u = f2ord(row[idx]);
        if (u > tau) {
            int p = atomicAdd(&s_cg, 1);
            if (p < K_TOP) sel[p] = idx;
        } else if (u == tau) {
            int p = atomicAdd(&s_ce, 1);
            if (p < EQ_CAP) eq[p] = idx;
        }
    }
    __syncthreads();

    const int cg = min(s_cg, K_TOP);    // == K_TOP - want_eq by construction
    int* dst = topk + (size_t)t * K_TOP;
    for (int i = tid; i < cg; i += 256) dst[i] = sel[i];

    if (tid == 0) {
        // take the `want_eq` smallest indices among the ties (partial selection)
        int ce = min(s_ce, EQ_CAP);
        int need = min(want_eq, ce);
        for (int s = 0; s < need; s++) {
            int best = s;
            for (int q = s + 1; q < ce; q++)
                if (eq[q] < eq[best]) best = q;
            int tmp = eq[s]; eq[s] = eq[best]; eq[best] = tmp;
            dst[cg + s] = eq[s];
        }
    }
}

// ============================================================================
// Gather + mean: mean[t][c] = (1/128) * sum_k patterns[topk[t][k]][c]
// One block (256 threads) per token; each thread owns 2 columns of P=512.
// ============================================================================
__global__ __launch_bounds__(256)
void gather_mean_kernel(const float* __restrict__ patterns,
                        const int* __restrict__ topk,
                        float* __restrict__ mean)
{
    const int t = blockIdx.x;
    const int tid = threadIdx.x;

    __shared__ int sidx[K_TOP];
    if (tid < K_TOP) sidx[tid] = topk[(size_t)t * K_TOP + tid];
    __syncthreads();

    float a0 = 0.0f, a1 = 0.0f;
#pragma unroll 4
    for (int k = 0; k < K_TOP; k++) {
        const float* prow = patterns + (size_t)sidx[k] * P_DIM;
        a0 += prow[tid];
        a1 += prow[tid + 256];
    }
    mean[(size_t)t * P_DIM + tid]       = a0 * (1.0f / K_TOP);
    mean[(size_t)t * P_DIM + tid + 256] = a1 * (1.0f / K_TOP);
}

// ============================================================================
// Launch
// ============================================================================
extern "C" void kernel_launch(void* const* d_in, const int* in_sizes, int n_in,
                              void* d_out, int out_size)
{
    const float* x        = (const float*)d_in[0];  // [T, D]
    const float* patterns = (const float*)d_in[1];  // [N, P]
    const float* alpha    = (const float*)d_in[2];  // [1]
    const float* enc_w    = (const float*)d_in[3];  // [P, D]
    const float* enc_b    = (const float*)d_in[4];  // [P]
    const float* dec_w    = (const float*)d_in[5];  // [D, P]
    const float* dec_b    = (const float*)d_in[6];  // [D]
    float* out = (float*)d_out;                     // [T, D]

    float *enc, *encn, *patn, *sim, *meanp;
    int* topk;
    cudaGetSymbolAddress((void**)&enc,   g_enc);
    cudaGetSymbolAddress((void**)&encn,  g_encn);
    cudaGetSymbolAddress((void**)&patn,  g_patn);
    cudaGetSymbolAddress((void**)&sim,   g_sim);
    cudaGetSymbolAddress((void**)&topk,  g_topk);
    cudaGetSymbolAddress((void**)&meanp, g_mean);

    // 1) encoder GEMM: enc[T,P] = x @ enc_w^T + enc_b
    {
        dim3 grid(P_DIM / 128, T_TOK / 128);
        gemm128_kernel<1><<<grid, 256>>>(x, enc_w, enc_b, enc,
                                         nullptr, nullptr, T_TOK, P_DIM, D_DIM);
    }
    // 2) normalize enc rows
    rownorm_kernel<<<T_TOK, 256>>>(enc, encn, P_DIM);
    // 3) normalize pattern rows
    rownorm_kernel<<<N_PAT, 256>>>(patterns, patn, P_DIM);
    // 4) sim GEMM: sim[T,N] = encn @ patn^T
    {
        dim3 grid(N_PAT / 128, T_TOK / 128);
        gemm128_kernel<0><<<grid, 256>>>(encn, patn, nullptr, sim,
                                         nullptr, nullptr, T_TOK, N_PAT, P_DIM);
    }
    // 5) exact top-128 per token
    topk_kernel<<<T_TOK, 256>>>(sim, topk);
    // 6) gather + mean over the 128 selected patterns
    gather_mean_kernel<<<T_TOK, 256>>>(patterns, topk, meanp);
    // 7) decoder GEMM + residual: out = x + alpha*(mean @ dec_w^T + dec_b)
    {
        dim3 grid(D_DIM / 128, T_TOK / 128);
        gemm128_kernel<2><<<grid, 256>>>(meanp, dec_w, dec_b, out,
                                         x, alpha, T_TOK, D_DIM, P_DIM);
    }
}

// round 6
// speedup vs baseline: 2.1985x; 2.1985x over previous
#include <cuda_runtime.h>
#include <cuda_bf16.h>
#include <cstdint>
#include <cstddef>

// ----------------------------------------------------------------------------
//   x[T,D] -> enc = x @ enc_w^T + enc_b            (T=4096, D=1024, P=512)
//   enc_n, pat_n = L2-normalized rows (eps 1e-8)
//   sim = enc_n @ pat_n^T                          [T, N]  N=65536
//   idx = top-128(sim); mean_pat = mean(patterns[idx])
//   out = x + alpha * (mean_pat @ dec_w^T + dec_b)
//
// sim GEMM: mma.sync bf16 (HMMA, compute_103-safe) with bf16x3 split
// (AhBh + AhBl + AlBh, fp32 accum) to preserve exact top-k ranking.
// ----------------------------------------------------------------------------

#define T_TOK 4096
#define D_DIM 1024
#define P_DIM 512
#define N_PAT 65536
#define K_TOP 128

// Static scratch (no runtime allocation).
__device__ float         g_enc [(size_t)T_TOK * P_DIM];
__device__ __nv_bfloat16 g_Ah  [(size_t)T_TOK * P_DIM];
__device__ __nv_bfloat16 g_Al  [(size_t)T_TOK * P_DIM];
__device__ __nv_bfloat16 g_Bh  [(size_t)N_PAT * P_DIM];
__device__ __nv_bfloat16 g_Bl  [(size_t)N_PAT * P_DIM];
__device__ float         g_sim [(size_t)T_TOK * N_PAT];   // 1 GiB
__device__ int           g_topk[(size_t)T_TOK * K_TOP];
__device__ float         g_mean[(size_t)T_TOK * P_DIM];

// ============================================================================
// PTX helpers — all compute_80-level (safe for compute_103 without 'a')
// ============================================================================
__device__ __forceinline__ uint32_t smem_to_u32(const void* p) {
    uint32_t a;
    asm("{ .reg .u64 t; cvta.to.shared.u64 t, %1; cvt.u32.u64 %0, t; }"
        : "=r"(a) : "l"(p));
    return a;
}

__device__ __forceinline__ void ldsm4(uint32_t& r0, uint32_t& r1,
                                      uint32_t& r2, uint32_t& r3, uint32_t a) {
    asm volatile("ldmatrix.sync.aligned.m8n8.x4.shared.b16 {%0,%1,%2,%3}, [%4];"
                 : "=r"(r0), "=r"(r1), "=r"(r2), "=r"(r3) : "r"(a));
}

__device__ __forceinline__ void mma16816(float* c,
                                         const uint32_t* a,
                                         const uint32_t* b) {
    asm volatile(
        "mma.sync.aligned.m16n8k16.row.col.f32.bf16.bf16.f32 "
        "{%0,%1,%2,%3}, {%4,%5,%6,%7}, {%8,%9}, {%0,%1,%2,%3};"
        : "+f"(c[0]), "+f"(c[1]), "+f"(c[2]), "+f"(c[3])
        : "r"(a[0]), "r"(a[1]), "r"(a[2]), "r"(a[3]), "r"(b[0]), "r"(b[1]));
}

#define CP_ASYNC16(dst_u32, src_ptr) \
    asm volatile("cp.async.cg.shared.global [%0], [%1], 16;" \
                 :: "r"(dst_u32), "l"(src_ptr))
#define CP_COMMIT() asm volatile("cp.async.commit_group;" ::: "memory")
#define CP_WAIT(n)  asm volatile("cp.async.wait_group %0;" :: "n"(n) : "memory")

// ============================================================================
// sim GEMM: sim[T,N] = (Ah+Al) @ (Bh+Bl)^T, fp32 accum, 3 HMMA terms.
// CTA tile 128x128, 8 warps (warp tile 32x64), K chunked by 32, double buffer.
//
// SMEM chunk layout per operand tile [128 rows x 32 k]:
//   16B chunk (row, c16) at byte offset row*80 + c16*16   (c16 = k/8, 0..3)
//   -> conflict-free for cp.async stores AND ldmatrix reads.
// Per-buffer: Ah | Al | Bh | Bl, each 128*80 = 10240 B  => 40960 B/buffer.
// ============================================================================
#define SIM_TILE_B   10240
#define SIM_BUF_B    40960
#define SIM_SMEM_B   81920

__device__ __forceinline__ void sim_cp_chunk(
    uint32_t sbase,
    const __nv_bfloat16* __restrict__ Ah, const __nv_bfloat16* __restrict__ Al,
    const __nv_bfloat16* __restrict__ Bh, const __nv_bfloat16* __restrict__ Bl,
    int m0, int n0, int c, int buf, int tid)
{
    const int kofs = c * 32;
    const uint32_t dbase = sbase + (uint32_t)buf * SIM_BUF_B;
#pragma unroll
    for (int t = 0; t < 4; t++) {
        const __nv_bfloat16* src = (t == 0) ? Ah : (t == 1) ? Al : (t == 2) ? Bh : Bl;
        const int rbase = (t < 2) ? m0 : n0;
#pragma unroll
        for (int i = 0; i < 2; i++) {
            int lin = i * 256 + tid;      // 512 chunks of 16B per tile
            int row = lin >> 2;           // 0..127
            int c16 = lin & 3;            // 0..3
            const void* g = src + (size_t)(rbase + row) * P_DIM + kofs + c16 * 8;
            uint32_t d = dbase + (uint32_t)t * SIM_TILE_B
                       + (uint32_t)(row * 80 + c16 * 16);
            CP_ASYNC16(d, g);
        }
    }
    CP_COMMIT();
}

__global__ __launch_bounds__(256)
void sim_mma_kernel(const __nv_bfloat16* __restrict__ Ah,
                    const __nv_bfloat16* __restrict__ Al,
                    const __nv_bfloat16* __restrict__ Bh,
                    const __nv_bfloat16* __restrict__ Bl,
                    float* __restrict__ sim)
{
    extern __shared__ char smem[];
    const uint32_t sbase = smem_to_u32(smem);
    const int tid = threadIdx.x;
    const int wid = tid >> 5;
    const int lane = tid & 31;
    const int m0 = blockIdx.x * 128;   // x fastest over M -> B tile shared in wave
    const int n0 = blockIdx.y * 128;
    const int warp_m = wid >> 1;       // 0..3
    const int warp_n = wid & 1;        // 0..1

    float acc[2][8][4];
#pragma unroll
    for (int mi = 0; mi < 2; mi++)
#pragma unroll
        for (int ni = 0; ni < 8; ni++)
#pragma unroll
            for (int q = 0; q < 4; q++) acc[mi][ni][q] = 0.0f;

    sim_cp_chunk(sbase, Ah, Al, Bh, Bl, m0, n0, 0, 0, tid);

    for (int c = 0; c < 16; c++) {
        if (c + 1 < 16) {
            sim_cp_chunk(sbase, Ah, Al, Bh, Bl, m0, n0, c + 1, (c + 1) & 1, tid);
            CP_WAIT(1);
        } else {
            CP_WAIT(0);
        }
        __syncthreads();

        const uint32_t ab = sbase + (uint32_t)(c & 1) * SIM_BUF_B;
        const uint32_t alb = ab + SIM_TILE_B;
        const uint32_t bhb = ab + 2 * SIM_TILE_B;
        const uint32_t blb = ab + 3 * SIM_TILE_B;

#pragma unroll
        for (int ks = 0; ks < 2; ks++) {
            // A fragments (2 m-tiles, high+low)
            uint32_t fah[2][4], fal[2][4];
            {
                const int arow = warp_m * 32 + (lane & 15);
                const int ac16 = ks * 2 + (lane >> 4);
#pragma unroll
                for (int mi = 0; mi < 2; mi++) {
                    uint32_t off = (uint32_t)((arow + mi * 16) * 80 + ac16 * 16);
                    ldsm4(fah[mi][0], fah[mi][1], fah[mi][2], fah[mi][3], ab + off);
                    ldsm4(fal[mi][0], fal[mi][1], fal[mi][2], fal[mi][3], alb + off);
                }
            }
            // B fragments (8 n-tiles, high+low) via x4 over n-tile pairs
            uint32_t fbh[8][2], fbl[8][2];
            {
                const int g = lane >> 3;
                const int brow = warp_n * 64 + (g >> 1) * 8 + (lane & 7);
                const int bc16 = ks * 2 + (g & 1);
#pragma unroll
                for (int np = 0; np < 4; np++) {
                    uint32_t off = (uint32_t)((brow + np * 16) * 80 + bc16 * 16);
                    uint32_t r0, r1, r2, r3;
                    ldsm4(r0, r1, r2, r3, bhb + off);
                    fbh[np * 2][0] = r0; fbh[np * 2][1] = r1;
                    fbh[np * 2 + 1][0] = r2; fbh[np * 2 + 1][1] = r3;
                    ldsm4(r0, r1, r2, r3, blb + off);
                    fbl[np * 2][0] = r0; fbl[np * 2][1] = r1;
                    fbl[np * 2 + 1][0] = r2; fbl[np * 2 + 1][1] = r3;
                }
            }
            // 3-term accumulation: AhBh + AhBl + AlBh
#pragma unroll
            for (int mi = 0; mi < 2; mi++)
#pragma unroll
                for (int ni = 0; ni < 8; ni++) {
                    mma16816(acc[mi][ni], fah[mi], fbh[ni]);
                    mma16816(acc[mi][ni], fah[mi], fbl[ni]);
                    mma16816(acc[mi][ni], fal[mi], fbh[ni]);
                }
        }
        __syncthreads();
    }

    // Epilogue: direct stores (float2), mma.m16n8 layout
    const int row = m0 + warp_m * 32 + (lane >> 2);
    const int colb = n0 + warp_n * 64 + (lane & 3) * 2;
#pragma unroll
    for (int mi = 0; mi < 2; mi++)
#pragma unroll
        for (int ni = 0; ni < 8; ni++) {
            float2 v01 = make_float2(acc[mi][ni][0], acc[mi][ni][1]);
            float2 v23 = make_float2(acc[mi][ni][2], acc[mi][ni][3]);
            *reinterpret_cast<float2*>(
                &sim[(size_t)(row + mi * 16) * N_PAT + colb + ni * 8]) = v01;
            *reinterpret_cast<float2*>(
                &sim[(size_t)(row + mi * 16 + 8) * N_PAT + colb + ni * 8]) = v23;
        }
}

// ============================================================================
// SIMT SGEMM for the small enc/dec GEMMs: C[M,N] = A[M,K] @ B[N,K]^T
// MODE 1: C = acc + bias[n];  MODE 2: C = resid + alpha*(acc + bias[n])
// ============================================================================
template <int MODE>
__global__ __launch_bounds__(256, 2)
void gemm128_kernel(const float* __restrict__ A, const float* __restrict__ B,
                    const float* __restrict__ bias, float* __restrict__ C,
                    const float* __restrict__ resid, const float* __restrict__ alpha,
                    int M, int N, int K)
{
    __shared__ float As[16][128];
    __shared__ float Bs[16][128];

    const int tid = threadIdx.x;
    const int m0 = blockIdx.y * 128;
    const int n0 = blockIdx.x * 128;
    const int tr = tid >> 4;
    const int tc = tid & 15;

    float acc[8][8];
#pragma unroll
    for (int i = 0; i < 8; i++)
#pragma unroll
        for (int j = 0; j < 8; j++) acc[i][j] = 0.0f;

    const int f0_row = tid >> 2;
    const int f0_c4  = tid & 3;
    const int f1_row = (tid + 256) >> 2;

    for (int k0 = 0; k0 < K; k0 += 16) {
        {
            float4 v0 = *reinterpret_cast<const float4*>(&A[(size_t)(m0 + f0_row) * K + k0 + 4 * f0_c4]);
            float4 v1 = *reinterpret_cast<const float4*>(&A[(size_t)(m0 + f1_row) * K + k0 + 4 * f0_c4]);
            As[4 * f0_c4 + 0][f0_row] = v0.x; As[4 * f0_c4 + 1][f0_row] = v0.y;
            As[4 * f0_c4 + 2][f0_row] = v0.z; As[4 * f0_c4 + 3][f0_row] = v0.w;
            As[4 * f0_c4 + 0][f1_row] = v1.x; As[4 * f0_c4 + 1][f1_row] = v1.y;
            As[4 * f0_c4 + 2][f1_row] = v1.z; As[4 * f0_c4 + 3][f1_row] = v1.w;
        }
        {
            float4 v0 = *reinterpret_cast<const float4*>(&B[(size_t)(n0 + f0_row) * K + k0 + 4 * f0_c4]);
            float4 v1 = *reinterpret_cast<const float4*>(&B[(size_t)(n0 + f1_row) * K + k0 + 4 * f0_c4]);
            Bs[4 * f0_c4 + 0][f0_row] = v0.x; Bs[4 * f0_c4 + 1][f0_row] = v0.y;
            Bs[4 * f0_c4 + 2][f0_row] = v0.z; Bs[4 * f0_c4 + 3][f0_row] = v0.w;
            Bs[4 * f0_c4 + 0][f1_row] = v1.x; Bs[4 * f0_c4 + 1][f1_row] = v1.y;
            Bs[4 * f0_c4 + 2][f1_row] = v1.z; Bs[4 * f0_c4 + 3][f1_row] = v1.w;
        }
        __syncthreads();

#pragma unroll
        for (int k = 0; k < 16; k++) {
            float ra[8], rb[8];
            float4 a0 = *reinterpret_cast<const float4*>(&As[k][tr * 8 + 0]);
            float4 a1 = *reinterpret_cast<const float4*>(&As[k][tr * 8 + 4]);
            float4 b0 = *reinterpret_cast<const float4*>(&Bs[k][tc * 8 + 0]);
            float4 b1 = *reinterpret_cast<const float4*>(&Bs[k][tc * 8 + 4]);
            ra[0] = a0.x; ra[1] = a0.y; ra[2] = a0.z; ra[3] = a0.w;
            ra[4] = a1.x; ra[5] = a1.y; ra[6] = a1.z; ra[7] = a1.w;
            rb[0] = b0.x; rb[1] = b0.y; rb[2] = b0.z; rb[3] = b0.w;
            rb[4] = b1.x; rb[5] = b1.y; rb[6] = b1.z; rb[7] = b1.w;
#pragma unroll
            for (int i = 0; i < 8; i++)
#pragma unroll
                for (int j = 0; j < 8; j++)
                    acc[i][j] = fmaf(ra[i], rb[j], acc[i][j]);
        }
        __syncthreads();
    }

    const float a_val = (MODE == 2) ? alpha[0] : 0.0f;
#pragma unroll
    for (int i = 0; i < 8; i++) {
        const int m = m0 + tr * 8 + i;
#pragma unroll
        for (int j = 0; j < 8; j++) {
            const int n = n0 + tc * 8 + j;
            const size_t off = (size_t)m * N + n;
            float v = acc[i][j];
            if (MODE == 1) v += bias[n];
            else if (MODE == 2) v = resid[off] + a_val * (v + bias[n]);
            C[off] = v;
        }
    }
}

// ============================================================================
// Fused row L2-normalize + bf16x2 split (cols = 512, 256 threads/row).
// ============================================================================
__global__ __launch_bounds__(256)
void rownorm_split_kernel(const float* __restrict__ in,
                          __nv_bfloat16* __restrict__ oh,
                          __nv_bfloat16* __restrict__ ol)
{
    const int r = blockIdx.x;
    const int tid = threadIdx.x;
    const float* row = in + (size_t)r * P_DIM;
    float v0 = row[tid], v1 = row[tid + 256];
    float ss = fmaf(v0, v0, v1 * v1);
#pragma unroll
    for (int o = 16; o > 0; o >>= 1) ss += __shfl_xor_sync(0xFFFFFFFFu, ss, o);
    __shared__ float wsum[8];
    if ((tid & 31) == 0) wsum[tid >> 5] = ss;
    __syncthreads();
    if (tid < 32) {
        float v = (tid < 8) ? wsum[tid] : 0.0f;
#pragma unroll
        for (int o = 4; o > 0; o >>= 1) v += __shfl_xor_sync(0xFFFFFFFFu, v, o);
        if (tid == 0) wsum[0] = v;
    }
    __syncthreads();
    const float inv = 1.0f / fmaxf(sqrtf(wsum[0]), 1e-8f);

    float n0 = v0 * inv, n1 = v1 * inv;
    __nv_bfloat16 h0 = __float2bfloat16(n0);
    __nv_bfloat16 h1 = __float2bfloat16(n1);
    __nv_bfloat16 l0 = __float2bfloat16(n0 - __bfloat162float(h0));
    __nv_bfloat16 l1 = __float2bfloat16(n1 - __bfloat162float(h1));
    oh[(size_t)r * P_DIM + tid] = h0;
    oh[(size_t)r * P_DIM + tid + 256] = h1;
    ol[(size_t)r * P_DIM + tid] = l0;
    ol[(size_t)r * P_DIM + tid + 256] = l1;
}

// ============================================================================
// Exact top-128 per token: 4-pass radix select, ties -> smallest index.
// ============================================================================
__device__ __forceinline__ unsigned f2ord(float f) {
    unsigned x = __float_as_uint(f);
    return x ^ ((x & 0x80000000u) ? 0xFFFFFFFFu : 0x80000000u);
}

#define EQ_CAP 512

__global__ __launch_bounds__(256)
void topk_kernel(const float* __restrict__ sim, int* __restrict__ topk)
{
    const int t = blockIdx.x;
    const int tid = threadIdx.x;
    const float* row = sim + (size_t)t * N_PAT;

    __shared__ unsigned hist[256];
    __shared__ unsigned s_prefix;
    __shared__ int s_want;
    __shared__ int s_cg, s_ce;
    __shared__ int sel[K_TOP];
    __shared__ int eq[EQ_CAP];

    if (tid == 0) { s_prefix = 0u; s_want = K_TOP; }
    __syncthreads();

    for (int shift = 24; shift >= 0; shift -= 8) {
        hist[tid] = 0u;
        __syncthreads();
        const unsigned mask_hi = (shift == 24) ? 0u : ~((1u << (shift + 8)) - 1u);
        const unsigned pfx = s_prefix;
#pragma unroll 4
        for (int i = 0; i < N_PAT / 256; i++) {
            unsigned u = f2ord(row[i * 256 + tid]);
            if ((u & mask_hi) == pfx)
                atomicAdd(&hist[(u >> shift) & 255u], 1u);
        }
        __syncthreads();
        if (tid == 0) {
            unsigned cum = 0;
            int want = s_want;
            for (int b = 255; b >= 0; b--) {
                unsigned c = hist[b];
                if (cum + c >= (unsigned)want) {
                    s_prefix = pfx | ((unsigned)b << shift);
                    s_want = want - (int)cum;
                    break;
                }
                cum += c;
            }
        }
        __syncthreads();
    }

    const unsigned tau = s_prefix;
    const int want_eq = s_want;

    if (tid == 0) { s_cg = 0; s_ce = 0; }
    __syncthreads();

    for (int i = 0; i < N_PAT / 256; i++) {
        const int idx = i * 256 + tid;
        unsigned u = f2ord(row[idx]);
        if (u > tau) {
            int p = atomicAdd(&s_cg, 1);
            if (p < K_TOP) sel[p] = idx;
        } else if (u == tau) {
            int p = atomicAdd(&s_ce, 1);
            if (p < EQ_CAP) eq[p] = idx;
        }
    }
    __syncthreads();

    const int cg = min(s_cg, K_TOP);
    int* dst = topk + (size_t)t * K_TOP;
    for (int i = tid; i < cg; i += 256) dst[i] = sel[i];

    if (tid == 0) {
        int ce = min(s_ce, EQ_CAP);
        int need = min(want_eq, ce);
        for (int s = 0; s < need; s++) {
            int best = s;
            for (int q = s + 1; q < ce; q++)
                if (eq[q] < eq[best]) best = q;
            int tmp = eq[s]; eq[s] = eq[best]; eq[best] = tmp;
            dst[cg + s] = eq[s];
        }
    }
}

// ============================================================================
// Gather + mean over the 128 selected patterns.
// ============================================================================
__global__ __launch_bounds__(256)
void gather_mean_kernel(const float* __restrict__ patterns,
                        const int* __restrict__ topk,
                        float* __restrict__ mean)
{
    const int t = blockIdx.x;
    const int tid = threadIdx.x;

    __shared__ int sidx[K_TOP];
    if (tid < K_TOP) sidx[tid] = topk[(size_t)t * K_TOP + tid];
    __syncthreads();

    float a0 = 0.0f, a1 = 0.0f;
#pragma unroll 4
    for (int k = 0; k < K_TOP; k++) {
        const float* prow = patterns + (size_t)sidx[k] * P_DIM;
        a0 += prow[tid];
        a1 += prow[tid + 256];
    }
    mean[(size_t)t * P_DIM + tid]       = a0 * (1.0f / K_TOP);
    mean[(size_t)t * P_DIM + tid + 256] = a1 * (1.0f / K_TOP);
}

// ============================================================================
// Launch
// ============================================================================
extern "C" void kernel_launch(void* const* d_in, const int* in_sizes, int n_in,
                              void* d_out, int out_size)
{
    const float* x        = (const float*)d_in[0];
    const float* patterns = (const float*)d_in[1];
    const float* alpha    = (const float*)d_in[2];
    const float* enc_w    = (const float*)d_in[3];
    const float* enc_b    = (const float*)d_in[4];
    const float* dec_w    = (const float*)d_in[5];
    const float* dec_b    = (const float*)d_in[6];
    float* out = (float*)d_out;

    float *enc, *sim, *meanp;
    __nv_bfloat16 *Ah, *Al, *Bh, *Bl;
    int* topk;
    cudaGetSymbolAddress((void**)&enc,   g_enc);
    cudaGetSymbolAddress((void**)&Ah,    g_Ah);
    cudaGetSymbolAddress((void**)&Al,    g_Al);
    cudaGetSymbolAddress((void**)&Bh,    g_Bh);
    cudaGetSymbolAddress((void**)&Bl,    g_Bl);
    cudaGetSymbolAddress((void**)&sim,   g_sim);
    cudaGetSymbolAddress((void**)&topk,  g_topk);
    cudaGetSymbolAddress((void**)&meanp, g_mean);

    cudaFuncSetAttribute(sim_mma_kernel,
                         cudaFuncAttributeMaxDynamicSharedMemorySize, SIM_SMEM_B);

    // 1) encoder GEMM
    {
        dim3 grid(P_DIM / 128, T_TOK / 128);
        gemm128_kernel<1><<<grid, 256>>>(x, enc_w, enc_b, enc,
                                         nullptr, nullptr, T_TOK, P_DIM, D_DIM);
    }
    // 2) normalize + bf16x2 split
    rownorm_split_kernel<<<T_TOK, 256>>>(enc, Ah, Al);
    rownorm_split_kernel<<<N_PAT, 256>>>(patterns, Bh, Bl);
    // 3) sim GEMM on HMMA tensor cores (bf16x3)
    {
        dim3 grid(T_TOK / 128, N_PAT / 128);   // x over M for L2 B-reuse
        sim_mma_kernel<<<grid, 256, SIM_SMEM_B>>>(Ah, Al, Bh, Bl, sim);
    }
    // 4) exact top-128
    topk_kernel<<<T_TOK, 256>>>(sim, topk);
    // 5) gather + mean
    gather_mean_kernel<<<T_TOK, 256>>>(patterns, topk, meanp);
    // 6) decoder GEMM + residual
    {
        dim3 grid(D_DIM / 128, T_TOK / 128);
        gemm128_kernel<2><<<grid, 256>>>(meanp, dec_b ? dec_w : dec_w, dec_b, out,
                                         x, alpha, T_TOK, D_DIM, P_DIM);
    }
}

// round 7
// speedup vs baseline: 2.7203x; 1.2373x over previous
#include <cuda_runtime.h>
#include <cuda_bf16.h>
#include <cstdint>
#include <cstddef>

// ----------------------------------------------------------------------------
//   x[T,D] -> enc = x @ enc_w^T + enc_b            (T=4096, D=1024, P=512)
//   enc_n, pat_n = L2-normalized rows (eps 1e-8)
//   sim = enc_n @ pat_n^T                          [T, N]  N=65536
//   idx = top-128(sim); mean_pat = mean(patterns[idx])
//   out = x + alpha * (mean_pat @ dec_w^T + dec_b)
//
// sim GEMM: mma.sync bf16 (HMMA) with bf16x3 split (AhBh + AhBl + AlBh,
// fp32 accum). topk: 1-pass 4096-bin histogram + 1-pass candidate collect,
// exact select resolved in SMEM (2 gmem passes instead of 5).
// ----------------------------------------------------------------------------

#define T_TOK 4096
#define D_DIM 1024
#define P_DIM 512
#define N_PAT 65536
#define K_TOP 128

// Static scratch (no runtime allocation).
__device__ float         g_enc [(size_t)T_TOK * P_DIM];
__device__ __nv_bfloat16 g_Ah  [(size_t)T_TOK * P_DIM];
__device__ __nv_bfloat16 g_Al  [(size_t)T_TOK * P_DIM];
__device__ __nv_bfloat16 g_Bh  [(size_t)N_PAT * P_DIM];
__device__ __nv_bfloat16 g_Bl  [(size_t)N_PAT * P_DIM];
__device__ float         g_sim [(size_t)T_TOK * N_PAT];   // 1 GiB
__device__ int           g_topk[(size_t)T_TOK * K_TOP];
__device__ float         g_mean[(size_t)T_TOK * P_DIM];

// ============================================================================
// PTX helpers — all compute_80-level (safe for compute_103 without 'a')
// ============================================================================
__device__ __forceinline__ uint32_t smem_to_u32(const void* p) {
    uint32_t a;
    asm("{ .reg .u64 t; cvta.to.shared.u64 t, %1; cvt.u32.u64 %0, t; }"
        : "=r"(a) : "l"(p));
    return a;
}

__device__ __forceinline__ void ldsm4(uint32_t& r0, uint32_t& r1,
                                      uint32_t& r2, uint32_t& r3, uint32_t a) {
    asm volatile("ldmatrix.sync.aligned.m8n8.x4.shared.b16 {%0,%1,%2,%3}, [%4];"
                 : "=r"(r0), "=r"(r1), "=r"(r2), "=r"(r3) : "r"(a));
}

__device__ __forceinline__ void mma16816(float* c,
                                         const uint32_t* a,
                                         const uint32_t* b) {
    asm volatile(
        "mma.sync.aligned.m16n8k16.row.col.f32.bf16.bf16.f32 "
        "{%0,%1,%2,%3}, {%4,%5,%6,%7}, {%8,%9}, {%0,%1,%2,%3};"
        : "+f"(c[0]), "+f"(c[1]), "+f"(c[2]), "+f"(c[3])
        : "r"(a[0]), "r"(a[1]), "r"(a[2]), "r"(a[3]), "r"(b[0]), "r"(b[1]));
}

#define CP_ASYNC16(dst_u32, src_ptr) \
    asm volatile("cp.async.cg.shared.global [%0], [%1], 16;" \
                 :: "r"(dst_u32), "l"(src_ptr))
#define CP_COMMIT() asm volatile("cp.async.commit_group;" ::: "memory")
#define CP_WAIT(n)  asm volatile("cp.async.wait_group %0;" :: "n"(n) : "memory")

// ============================================================================
// sim GEMM: sim[T,N] = (Ah+Al) @ (Bh+Bl)^T, fp32 accum, 3 HMMA terms.
// CTA tile 128x128, 8 warps (warp tile 32x64), K chunked by 32, double buffer.
// SMEM chunk: 16B chunk (row, c16) at byte offset row*80 + c16*16.
// ============================================================================
#define SIM_TILE_B   10240
#define SIM_BUF_B    40960
#define SIM_SMEM_B   81920

__device__ __forceinline__ void sim_cp_chunk(
    uint32_t sbase,
    const __nv_bfloat16* __restrict__ Ah, const __nv_bfloat16* __restrict__ Al,
    const __nv_bfloat16* __restrict__ Bh, const __nv_bfloat16* __restrict__ Bl,
    int m0, int n0, int c, int buf, int tid)
{
    const int kofs = c * 32;
    const uint32_t dbase = sbase + (uint32_t)buf * SIM_BUF_B;
#pragma unroll
    for (int t = 0; t < 4; t++) {
        const __nv_bfloat16* src = (t == 0) ? Ah : (t == 1) ? Al : (t == 2) ? Bh : Bl;
        const int rbase = (t < 2) ? m0 : n0;
#pragma unroll
        for (int i = 0; i < 2; i++) {
            int lin = i * 256 + tid;      // 512 chunks of 16B per tile
            int row = lin >> 2;           // 0..127
            int c16 = lin & 3;            // 0..3
            const void* g = src + (size_t)(rbase + row) * P_DIM + kofs + c16 * 8;
            uint32_t d = dbase + (uint32_t)t * SIM_TILE_B
                       + (uint32_t)(row * 80 + c16 * 16);
            CP_ASYNC16(d, g);
        }
    }
    CP_COMMIT();
}

__global__ __launch_bounds__(256)
void sim_mma_kernel(const __nv_bfloat16* __restrict__ Ah,
                    const __nv_bfloat16* __restrict__ Al,
                    const __nv_bfloat16* __restrict__ Bh,
                    const __nv_bfloat16* __restrict__ Bl,
                    float* __restrict__ sim)
{
    extern __shared__ char smem[];
    const uint32_t sbase = smem_to_u32(smem);
    const int tid = threadIdx.x;
    const int wid = tid >> 5;
    const int lane = tid & 31;
    const int m0 = blockIdx.x * 128;   // x fastest over M -> B tile shared in wave
    const int n0 = blockIdx.y * 128;
    const int warp_m = wid >> 1;       // 0..3
    const int warp_n = wid & 1;        // 0..1

    float acc[2][8][4];
#pragma unroll
    for (int mi = 0; mi < 2; mi++)
#pragma unroll
        for (int ni = 0; ni < 8; ni++)
#pragma unroll
            for (int q = 0; q < 4; q++) acc[mi][ni][q] = 0.0f;

    sim_cp_chunk(sbase, Ah, Al, Bh, Bl, m0, n0, 0, 0, tid);

    for (int c = 0; c < 16; c++) {
        if (c + 1 < 16) {
            sim_cp_chunk(sbase, Ah, Al, Bh, Bl, m0, n0, c + 1, (c + 1) & 1, tid);
            CP_WAIT(1);
        } else {
            CP_WAIT(0);
        }
        __syncthreads();

        const uint32_t ab = sbase + (uint32_t)(c & 1) * SIM_BUF_B;
        const uint32_t alb = ab + SIM_TILE_B;
        const uint32_t bhb = ab + 2 * SIM_TILE_B;
        const uint32_t blb = ab + 3 * SIM_TILE_B;

#pragma unroll
        for (int ks = 0; ks < 2; ks++) {
            uint32_t fah[2][4], fal[2][4];
            {
                const int arow = warp_m * 32 + (lane & 15);
                const int ac16 = ks * 2 + (lane >> 4);
#pragma unroll
                for (int mi = 0; mi < 2; mi++) {
                    uint32_t off = (uint32_t)((arow + mi * 16) * 80 + ac16 * 16);
                    ldsm4(fah[mi][0], fah[mi][1], fah[mi][2], fah[mi][3], ab + off);
                    ldsm4(fal[mi][0], fal[mi][1], fal[mi][2], fal[mi][3], alb + off);
                }
            }
            uint32_t fbh[8][2], fbl[8][2];
            {
                const int g = lane >> 3;
                const int brow = warp_n * 64 + (g >> 1) * 8 + (lane & 7);
                const int bc16 = ks * 2 + (g & 1);
#pragma unroll
                for (int np = 0; np < 4; np++) {
                    uint32_t off = (uint32_t)((brow + np * 16) * 80 + bc16 * 16);
                    uint32_t r0, r1, r2, r3;
                    ldsm4(r0, r1, r2, r3, bhb + off);
                    fbh[np * 2][0] = r0; fbh[np * 2][1] = r1;
                    fbh[np * 2 + 1][0] = r2; fbh[np * 2 + 1][1] = r3;
                    ldsm4(r0, r1, r2, r3, blb + off);
                    fbl[np * 2][0] = r0; fbl[np * 2][1] = r1;
                    fbl[np * 2 + 1][0] = r2; fbl[np * 2 + 1][1] = r3;
                }
            }
#pragma unroll
            for (int mi = 0; mi < 2; mi++)
#pragma unroll
                for (int ni = 0; ni < 8; ni++) {
                    mma16816(acc[mi][ni], fah[mi], fbh[ni]);
                    mma16816(acc[mi][ni], fah[mi], fbl[ni]);
                    mma16816(acc[mi][ni], fal[mi], fbh[ni]);
                }
        }
        __syncthreads();
    }

    const int row = m0 + warp_m * 32 + (lane >> 2);
    const int colb = n0 + warp_n * 64 + (lane & 3) * 2;
#pragma unroll
    for (int mi = 0; mi < 2; mi++)
#pragma unroll
        for (int ni = 0; ni < 8; ni++) {
            float2 v01 = make_float2(acc[mi][ni][0], acc[mi][ni][1]);
            float2 v23 = make_float2(acc[mi][ni][2], acc[mi][ni][3]);
            *reinterpret_cast<float2*>(
                &sim[(size_t)(row + mi * 16) * N_PAT + colb + ni * 8]) = v01;
            *reinterpret_cast<float2*>(
                &sim[(size_t)(row + mi * 16 + 8) * N_PAT + colb + ni * 8]) = v23;
        }
}

// ============================================================================
// SIMT SGEMM for the small enc/dec GEMMs: C[M,N] = A[M,K] @ B[N,K]^T
// MODE 1: C = acc + bias[n];  MODE 2: C = resid + alpha*(acc + bias[n])
// ============================================================================
template <int MODE>
__global__ __launch_bounds__(256, 2)
void gemm128_kernel(const float* __restrict__ A, const float* __restrict__ B,
                    const float* __restrict__ bias, float* __restrict__ C,
                    const float* __restrict__ resid, const float* __restrict__ alpha,
                    int M, int N, int K)
{
    __shared__ float As[16][128];
    __shared__ float Bs[16][128];

    const int tid = threadIdx.x;
    const int m0 = blockIdx.y * 128;
    const int n0 = blockIdx.x * 128;
    const int tr = tid >> 4;
    const int tc = tid & 15;

    float acc[8][8];
#pragma unroll
    for (int i = 0; i < 8; i++)
#pragma unroll
        for (int j = 0; j < 8; j++) acc[i][j] = 0.0f;

    const int f0_row = tid >> 2;
    const int f0_c4  = tid & 3;
    const int f1_row = (tid + 256) >> 2;

    for (int k0 = 0; k0 < K; k0 += 16) {
        {
            float4 v0 = *reinterpret_cast<const float4*>(&A[(size_t)(m0 + f0_row) * K + k0 + 4 * f0_c4]);
            float4 v1 = *reinterpret_cast<const float4*>(&A[(size_t)(m0 + f1_row) * K + k0 + 4 * f0_c4]);
            As[4 * f0_c4 + 0][f0_row] = v0.x; As[4 * f0_c4 + 1][f0_row] = v0.y;
            As[4 * f0_c4 + 2][f0_row] = v0.z; As[4 * f0_c4 + 3][f0_row] = v0.w;
            As[4 * f0_c4 + 0][f1_row] = v1.x; As[4 * f0_c4 + 1][f1_row] = v1.y;
            As[4 * f0_c4 + 2][f1_row] = v1.z; As[4 * f0_c4 + 3][f1_row] = v1.w;
        }
        {
            float4 v0 = *reinterpret_cast<const float4*>(&B[(size_t)(n0 + f0_row) * K + k0 + 4 * f0_c4]);
            float4 v1 = *reinterpret_cast<const float4*>(&B[(size_t)(n0 + f1_row) * K + k0 + 4 * f0_c4]);
            Bs[4 * f0_c4 + 0][f0_row] = v0.x; Bs[4 * f0_c4 + 1][f0_row] = v0.y;
            Bs[4 * f0_c4 + 2][f0_row] = v0.z; Bs[4 * f0_c4 + 3][f0_row] = v0.w;
            Bs[4 * f0_c4 + 0][f1_row] = v1.x; Bs[4 * f0_c4 + 1][f1_row] = v1.y;
            Bs[4 * f0_c4 + 2][f1_row] = v1.z; Bs[4 * f0_c4 + 3][f1_row] = v1.w;
        }
        __syncthreads();

#pragma unroll
        for (int k = 0; k < 16; k++) {
            float ra[8], rb[8];
            float4 a0 = *reinterpret_cast<const float4*>(&As[k][tr * 8 + 0]);
            float4 a1 = *reinterpret_cast<const float4*>(&As[k][tr * 8 + 4]);
            float4 b0 = *reinterpret_cast<const float4*>(&Bs[k][tc * 8 + 0]);
            float4 b1 = *reinterpret_cast<const float4*>(&Bs[k][tc * 8 + 4]);
            ra[0] = a0.x; ra[1] = a0.y; ra[2] = a0.z; ra[3] = a0.w;
            ra[4] = a1.x; ra[5] = a1.y; ra[6] = a1.z; ra[7] = a1.w;
            rb[0] = b0.x; rb[1] = b0.y; rb[2] = b0.z; rb[3] = b0.w;
            rb[4] = b1.x; rb[5] = b1.y; rb[6] = b1.z; rb[7] = b1.w;
#pragma unroll
            for (int i = 0; i < 8; i++)
#pragma unroll
                for (int j = 0; j < 8; j++)
                    acc[i][j] = fmaf(ra[i], rb[j], acc[i][j]);
        }
        __syncthreads();
    }

    const float a_val = (MODE == 2) ? alpha[0] : 0.0f;
#pragma unroll
    for (int i = 0; i < 8; i++) {
        const int m = m0 + tr * 8 + i;
#pragma unroll
        for (int j = 0; j < 8; j++) {
            const int n = n0 + tc * 8 + j;
            const size_t off = (size_t)m * N + n;
            float v = acc[i][j];
            if (MODE == 1) v += bias[n];
            else if (MODE == 2) v = resid[off] + a_val * (v + bias[n]);
            C[off] = v;
        }
    }
}

// ============================================================================
// Fused row L2-normalize + bf16x2 split (cols = 512, 256 threads/row).
// ============================================================================
__global__ __launch_bounds__(256)
void rownorm_split_kernel(const float* __restrict__ in,
                          __nv_bfloat16* __restrict__ oh,
                          __nv_bfloat16* __restrict__ ol)
{
    const int r = blockIdx.x;
    const int tid = threadIdx.x;
    const float* row = in + (size_t)r * P_DIM;
    float v0 = row[tid], v1 = row[tid + 256];
    float ss = fmaf(v0, v0, v1 * v1);
#pragma unroll
    for (int o = 16; o > 0; o >>= 1) ss += __shfl_xor_sync(0xFFFFFFFFu, ss, o);
    __shared__ float wsum[8];
    if ((tid & 31) == 0) wsum[tid >> 5] = ss;
    __syncthreads();
    if (tid < 32) {
        float v = (tid < 8) ? wsum[tid] : 0.0f;
#pragma unroll
        for (int o = 4; o > 0; o >>= 1) v += __shfl_xor_sync(0xFFFFFFFFu, v, o);
        if (tid == 0) wsum[0] = v;
    }
    __syncthreads();
    const float inv = 1.0f / fmaxf(sqrtf(wsum[0]), 1e-8f);

    float n0 = v0 * inv, n1 = v1 * inv;
    __nv_bfloat16 h0 = __float2bfloat16(n0);
    __nv_bfloat16 h1 = __float2bfloat16(n1);
    __nv_bfloat16 l0 = __float2bfloat16(n0 - __bfloat162float(h0));
    __nv_bfloat16 l1 = __float2bfloat16(n1 - __bfloat162float(h1));
    oh[(size_t)r * P_DIM + tid] = h0;
    oh[(size_t)r * P_DIM + tid + 256] = h1;
    ol[(size_t)r * P_DIM + tid] = l0;
    ol[(size_t)r * P_DIM + tid + 256] = l1;
}

// ============================================================================
// Exact top-128 per token, 2 gmem passes:
//   pass 1: 4096-bin histogram on top-12 bits of order-preserving key
//   pass 2: collect candidates >= boundary-bin floor into SMEM (~270 expected)
//   then exact 3-pass radix select over SMEM candidates; ties -> smallest idx.
// Output SET is identical to the previous 5-pass version.
// ============================================================================
__device__ __forceinline__ unsigned f2ord(float f) {
    unsigned x = __float_as_uint(f);
    return x ^ ((x & 0x80000000u) ? 0xFFFFFFFFu : 0x80000000u);
}

#define TK_BINS 4096
#define TK_CAP  2048
#define TK_EQ   64

__global__ __launch_bounds__(256)
void topk_kernel(const float* __restrict__ sim, int* __restrict__ topk)
{
    const int t = blockIdx.x;
    const int tid = threadIdx.x;
    const float* row = sim + (size_t)t * N_PAT;

    __shared__ unsigned hist[TK_BINS];
    __shared__ unsigned ukey[TK_CAP];
    __shared__ int      uidx[TK_CAP];
    __shared__ unsigned h2[256];
    __shared__ int s_b, s_cg, s_cnt;
    __shared__ unsigned s_prefix;
    __shared__ int s_want;
    __shared__ int s_out, s_ce;
    __shared__ int eqidx[TK_EQ];

    for (int i = tid; i < TK_BINS; i += 256) hist[i] = 0u;
    __syncthreads();

    // pass 1: 12-bit histogram
#pragma unroll 4
    for (int i = 0; i < N_PAT / 256; i++) {
        unsigned u = f2ord(row[i * 256 + tid]);
        atomicAdd(&hist[u >> 20], 1u);
    }
    __syncthreads();

    // find boundary bin via descending suffix scan (thread tid owns 16 bins)
    const int base = 4095 - tid * 16;
    unsigned lsum = 0;
#pragma unroll
    for (int j = 0; j < 16; j++) lsum += hist[base - j];
    h2[tid] = lsum;
    __syncthreads();
    if (tid == 0) {
        unsigned run = 0;
        for (int i = 0; i < 256; i++) { unsigned c = h2[i]; h2[i] = run; run += c; }
    }
    __syncthreads();
    {
        unsigned run = h2[tid];
        if (run < (unsigned)K_TOP && run + lsum >= (unsigned)K_TOP) {
            unsigned r = run;
#pragma unroll
            for (int j = 0; j < 16; j++) {
                unsigned c = hist[base - j];
                if (r + c >= (unsigned)K_TOP) { s_b = base - j; s_cg = (int)r; break; }
                r += c;
            }
        }
    }
    if (tid == 0) s_cnt = 0;
    __syncthreads();

    const int b = s_b;
    const unsigned floorkey = ((unsigned)b) << 20;

    // pass 2: collect candidates
#pragma unroll 4
    for (int i = 0; i < N_PAT / 256; i++) {
        const int idx = i * 256 + tid;
        unsigned u = f2ord(row[idx]);
        if (u >= floorkey) {
            int p = atomicAdd(&s_cnt, 1);
            if (p < TK_CAP) { ukey[p] = u; uidx[p] = idx; }
        }
    }
    __syncthreads();
    const int cnt = min(s_cnt, TK_CAP);

    // exact radix select over candidates in bin b (low 20 bits: 8+8+4)
    if (tid == 0) { s_prefix = floorkey; s_want = K_TOP - s_cg; }
    __syncthreads();

    const int      shifts[3] = {12, 4, 0};
    const unsigned nbinsv[3] = {256u, 256u, 16u};
    const unsigned dmasks[3] = {0xFFF00000u, 0xFFFFF000u, 0xFFFFFFF0u};
#pragma unroll
    for (int p = 0; p < 3; p++) {
        h2[tid] = 0u;
        __syncthreads();
        const unsigned dm = dmasks[p];
        const unsigned pfx = s_prefix;
        const int sh = shifts[p];
        const unsigned nb = nbinsv[p];
        for (int i = tid; i < cnt; i += 256) {
            unsigned u = ukey[i];
            if ((u & dm) == pfx)
                atomicAdd(&h2[(u >> sh) & (nb - 1u)], 1u);
        }
        __syncthreads();
        if (tid == 0) {
            unsigned run = 0;
            int want = s_want;
            for (int bin = (int)nb - 1; bin >= 0; bin--) {
                unsigned c = h2[bin];
                if (run + c >= (unsigned)want) {
                    s_prefix = pfx | ((unsigned)bin << sh);
                    s_want = want - (int)run;
                    break;
                }
                run += c;
            }
        }
        __syncthreads();
    }

    const unsigned tau = s_prefix;
    const int want_eq = s_want;

    if (tid == 0) { s_out = 0; s_ce = 0; }
    __syncthreads();

    int* dst = topk + (size_t)t * K_TOP;
    for (int i = tid; i < cnt; i += 256) {
        unsigned u = ukey[i];
        if (u > tau) {
            int p = atomicAdd(&s_out, 1);
            if (p < K_TOP) dst[p] = uidx[i];
        } else if (u == tau) {
            int p = atomicAdd(&s_ce, 1);
            if (p < TK_EQ) eqidx[p] = uidx[i];
        }
    }
    __syncthreads();

    if (tid == 0) {
        const int cg = min(s_out, K_TOP);       // == K_TOP - want_eq
        int ce = min(s_ce, TK_EQ);
        int need = min(want_eq, ce);
        for (int s = 0; s < need; s++) {        // smallest indices among ties
            int best = s;
            for (int q = s + 1; q < ce; q++)
                if (eqidx[q] < eqidx[best]) best = q;
            int tmp = eqidx[s]; eqidx[s] = eqidx[best]; eqidx[best] = tmp;
            dst[cg + s] = eqidx[s];
        }
    }
}

// ============================================================================
// Gather + mean over the 128 selected patterns.
// ============================================================================
__global__ __launch_bounds__(256)
void gather_mean_kernel(const float* __restrict__ patterns,
                        const int* __restrict__ topk,
                        float* __restrict__ mean)
{
    const int t = blockIdx.x;
    const int tid = threadIdx.x;

    __shared__ int sidx[K_TOP];
    if (tid < K_TOP) sidx[tid] = topk[(size_t)t * K_TOP + tid];
    __syncthreads();

    float a0 = 0.0f, a1 = 0.0f;
#pragma unroll 4
    for (int k = 0; k < K_TOP; k++) {
        const float* prow = patterns + (size_t)sidx[k] * P_DIM;
        a0 += prow[tid];
        a1 += prow[tid + 256];
    }
    mean[(size_t)t * P_DIM + tid]       = a0 * (1.0f / K_TOP);
    mean[(size_t)t * P_DIM + tid + 256] = a1 * (1.0f / K_TOP);
}

// ============================================================================
// Launch
// ============================================================================
extern "C" void kernel_launch(void* const* d_in, const int* in_sizes, int n_in,
                              void* d_out, int out_size)
{
    const float* x        = (const float*)d_in[0];
    const float* patterns = (const float*)d_in[1];
    const float* alpha    = (const float*)d_in[2];
    const float* enc_w    = (const float*)d_in[3];
    const float* enc_b    = (const float*)d_in[4];
    const float* dec_w    = (const float*)d_in[5];
    const float* dec_b    = (const float*)d_in[6];
    float* out = (float*)d_out;

    float *enc, *sim, *meanp;
    __nv_bfloat16 *Ah, *Al, *Bh, *Bl;
    int* topk;
    cudaGetSymbolAddress((void**)&enc,   g_enc);
    cudaGetSymbolAddress((void**)&Ah,    g_Ah);
    cudaGetSymbolAddress((void**)&Al,    g_Al);
    cudaGetSymbolAddress((void**)&Bh,    g_Bh);
    cudaGetSymbolAddress((void**)&Bl,    g_Bl);
    cudaGetSymbolAddress((void**)&sim,   g_sim);
    cudaGetSymbolAddress((void**)&topk,  g_topk);
    cudaGetSymbolAddress((void**)&meanp, g_mean);

    cudaFuncSetAttribute(sim_mma_kernel,
                         cudaFuncAttributeMaxDynamicSharedMemorySize, SIM_SMEM_B);

    // 1) encoder GEMM
    {
        dim3 grid(P_DIM / 128, T_TOK / 128);
        gemm128_kernel<1><<<grid, 256>>>(x, enc_w, enc_b, enc,
                                         nullptr, nullptr, T_TOK, P_DIM, D_DIM);
    }
    // 2) normalize + bf16x2 split
    rownorm_split_kernel<<<T_TOK, 256>>>(enc, Ah, Al);
    rownorm_split_kernel<<<N_PAT, 256>>>(patterns, Bh, Bl);
    // 3) sim GEMM on HMMA tensor cores (bf16x3)
    {
        dim3 grid(T_TOK / 128, N_PAT / 128);   // x over M for L2 B-reuse
        sim_mma_kernel<<<grid, 256, SIM_SMEM_B>>>(Ah, Al, Bh, Bl, sim);
    }
    // 4) exact top-128 (2-pass)
    topk_kernel<<<T_TOK, 256>>>(sim, topk);
    // 5) gather + mean
    gather_mean_kernel<<<T_TOK, 256>>>(patterns, topk, meanp);
    // 6) decoder GEMM + residual
    {
        dim3 grid(D_DIM / 128, T_TOK / 128);
        gemm128_kernel<2><<<grid, 256>>>(meanp, dec_w, dec_b, out,
                                         x, alpha, T_TOK, D_DIM, P_DIM);
    }
}